// round 16
// baseline (speedup 1.0000x reference)
#include <cuda_runtime.h>
#include <cuda_fp16.h>
#include <mma.h>

using namespace nvcuda;

// Problem constants
#define Bc 4
#define Hc 16
#define Sc 2048
#define Dc 128
#define NTOT (Bc * Hc * Sc * Dc)

// Tiling (round-15 winning shape)
#define TQ 64
#define TK 64
#define THREADS 512
#define NKT (Sc / TK)
#define LDH  136
#define PLDF 68
#define PLDH 72
#define OLDF 132

// smem layout (bytes)
#define QH_OFF    0
#define KV_OFF    (TQ * LDH * 2)                 // 17408
#define KVSTAGE   (2 * TK * LDH * 2)             // 34816 per stage
#define PSF_OFF   (KV_OFF + 2 * KVSTAGE)         // 87040
#define PSH_OFF   (PSF_OFF + TQ * PLDF * 4)      // 104448
#define LROWP_OFF (PSH_OFF + TQ * PLDH * 2)      // 113664
#define LROWI_OFF (LROWP_OFF + 256 * 4)          // 114688
#define SMEM_BYTES (LROWI_OFF + 64 * 4)          // 114944 -> 2 CTAs/SM

// fp16 copies of Q/K/V (pre-pass output). Static device scratch: allowed.
__device__ __half g_qh[NTOT];
__device__ __half g_kh[NTOT];
__device__ __half g_vh[NTOT];

__device__ __forceinline__ void cp_async16(void* s, const void* g) {
    unsigned sa = (unsigned)__cvta_generic_to_shared(s);
    asm volatile("cp.async.cg.shared.global [%0],[%1],16;\n" ::"r"(sa), "l"(g));
}
__device__ __forceinline__ void cp_commit() { asm volatile("cp.async.commit_group;\n"); }
__device__ __forceinline__ void cp_wait0() { asm volatile("cp.async.wait_group 0;\n"); }
__device__ __forceinline__ void cp_wait1() { asm volatile("cp.async.wait_group 1;\n"); }
__device__ __forceinline__ void bar_sync(int id, int cnt) {
    asm volatile("bar.sync %0, %1;" ::"r"(id), "r"(cnt) : "memory");
}

// exp for small x via degree-6 Taylor; __expf fallback for the rare tail
__device__ __forceinline__ float exp_small(float x) {
    float pe = 1.388888889e-3f;
    pe = fmaf(pe, x, 8.333333333e-3f);
    pe = fmaf(pe, x, 4.166666667e-2f);
    pe = fmaf(pe, x, 1.666666667e-1f);
    pe = fmaf(pe, x, 0.5f);
    pe = fmaf(pe, x, 1.0f);
    pe = fmaf(pe, x, 1.0f);
    if (fabsf(x) > 0.5f) {
        pe = __expf(x);
    }
    return pe;
}

// Pre-pass: fp32 to fp16 RN conversion of Q, K, V (measured 84% DRAM, 39us)
__global__ __launch_bounds__(256)
void cvt_kernel(const float4* __restrict__ q,
                const float4* __restrict__ k,
                const float4* __restrict__ v) {
    int i = blockIdx.x * blockDim.x + threadIdx.x;
    float4 a;
    __half2 h0, h1;
    uint2 u;

    a = q[i];
    h0 = __floats2half2_rn(a.x, a.y);
    h1 = __floats2half2_rn(a.z, a.w);
    u.x = *(unsigned*)&h0;
    u.y = *(unsigned*)&h1;
    ((uint2*)g_qh)[i] = u;

    a = k[i];
    h0 = __floats2half2_rn(a.x, a.y);
    h1 = __floats2half2_rn(a.z, a.w);
    u.x = *(unsigned*)&h0;
    u.y = *(unsigned*)&h1;
    ((uint2*)g_kh)[i] = u;

    a = v[i];
    h0 = __floats2half2_rn(a.x, a.y);
    h1 = __floats2half2_rn(a.z, a.w);
    u.x = *(unsigned*)&h0;
    u.y = *(unsigned*)&h1;
    ((uint2*)g_vh)[i] = u;
}

__global__ __launch_bounds__(THREADS, 2)
void attn_main_kernel(const float* __restrict__ mg,
                      float* __restrict__ outg,
                      float* __restrict__ attng) {
    extern __shared__ char sm[];
    __half* Qh    = (__half*)(sm + QH_OFF);
    __half* kvs   = (__half*)(sm + KV_OFF);
    float*  Psf   = (float*)(sm + PSF_OFF);
    __half* Psh   = (__half*)(sm + PSH_OFF);
    float*  lrowP = (float*)(sm + LROWP_OFF);   // [4][64] per-tj row partials
    float*  lrowI = (float*)(sm + LROWI_OFF);   // [64] reciprocals

    const int hh = blockIdx.x;   // head fastest: mask slice L2-reused across heads
    const int qt = blockIdx.y;
    const int b  = blockIdx.z;
    const int tid  = threadIdx.x;
    const int lane = tid & 31;
    const int warp = tid >> 5;
    const int q0   = qt * TQ;

    const long long bh = (long long)b * Hc + hh;
    const __half* qptr  = g_qh + (bh * Sc + q0) * (long long)Dc;
    const __half* kbase = g_kh + bh * Sc * (long long)Dc;
    const __half* vbase = g_vh + bh * Sc * (long long)Dc;

    // Prologue group 0: Q tile + K0/V0 into stage 0
    {
        int r = tid >> 4;
        int c8 = (tid & 15) * 8;
        cp_async16(Qh + r * LDH + c8, qptr + (long long)r * Dc + c8);
        cp_async16(kvs + r * LDH + c8, kbase + (long long)r * Dc + c8);
        cp_async16(kvs + TK * LDH + r * LDH + c8, vbase + (long long)r * Dc + c8);
        r += 32;
        cp_async16(Qh + r * LDH + c8, qptr + (long long)r * Dc + c8);
        cp_async16(kvs + r * LDH + c8, kbase + (long long)r * Dc + c8);
        cp_async16(kvs + TK * LDH + r * LDH + c8, vbase + (long long)r * Dc + c8);
    }
    cp_commit();

    const int ti = warp >> 2;
    const int tj = warp & 3;

    wmma::fragment<wmma::accumulator, 16, 16, 16, float> Oacc[2];
    wmma::fill_fragment(Oacc[0], 0.0f);
    wmma::fill_fragment(Oacc[1], 0.0f);
    float lsum = 0.0f;   // per-lane partial over this warp's subtile columns

    // Warp-private exp mapping: lane covers row wr, 8 cols starting at wc
    const int wr = ti * 16 + (lane >> 1);          // global row in the 64-row tile
    const int wc = tj * 16 + (lane & 1) * 8;       // col within the 64-key tile
    const long long mwbase =
        ((long long)b * Sc + q0 + wr) * (long long)Sc + wc;
    float* awbase = attng ? (attng + (bh * Sc + q0 + wr) * (long long)Sc + wc)
                          : nullptr;

    for (int kt = 0; kt < NKT; ++kt) {
        // Mask prefetch for tile kt (data-independent; hides under QK)
        float4 pm0 = *(const float4*)(mg + mwbase + (long long)kt * TK);
        float4 pm1 = *(const float4*)(mg + mwbase + (long long)kt * TK + 4);

        __syncthreads();   // all warps done reading the stage we refill next

        if (kt + 1 < NKT) {
            const __half* kp = kbase + (long long)(kt + 1) * TK * Dc;
            const __half* vp = vbase + (long long)(kt + 1) * TK * Dc;
            __half* kd = kvs + ((kt + 1) & 1) * (KVSTAGE / 2);
            int r = tid >> 4;
            int c8 = (tid & 15) * 8;
            cp_async16(kd + r * LDH + c8, kp + (long long)r * Dc + c8);
            cp_async16(kd + TK * LDH + r * LDH + c8, vp + (long long)r * Dc + c8);
            r += 32;
            cp_async16(kd + r * LDH + c8, kp + (long long)r * Dc + c8);
            cp_async16(kd + TK * LDH + r * LDH + c8, vp + (long long)r * Dc + c8);
            cp_commit();
            cp_wait1();    // stage kt arrived; stage kt+1 still in flight
        } else {
            cp_wait0();
        }
        __syncthreads();   // stage kt (and Q on first iter) visible to all warps

        const __half* Kc = kvs + (kt & 1) * (KVSTAGE / 2);
        const __half* Vc = Kc + TK * LDH;

        // Scores: S = Q * K^T for this warp's 16x16 subtile
        {
            wmma::fragment<wmma::accumulator, 16, 16, 16, float> Sacc;
            wmma::fill_fragment(Sacc, 0.0f);
            #pragma unroll
            for (int k = 0; k < Dc / 16; ++k) {
                wmma::fragment<wmma::matrix_a, 16, 16, 16, __half, wmma::row_major> af;
                wmma::fragment<wmma::matrix_b, 16, 16, 16, __half, wmma::col_major> bf;
                wmma::load_matrix_sync(af, Qh + ti * 16 * LDH + k * 16, LDH);
                wmma::load_matrix_sync(bf, Kc + tj * 16 * LDH + k * 16, LDH);
                wmma::mma_sync(Sacc, af, bf, Sacc);
            }
            wmma::store_matrix_sync(Psf + ti * 16 * PLDF + tj * 16, Sacc, PLDF,
                                    wmma::mem_row_major);
        }
        __syncwarp();      // Psf subtile is warp-private: warp sync suffices

        // Elementwise on own subtile: p = mask ? 0 : exp(s/128); attn; P->fp16
        {
            const float* srow = Psf + wr * PLDF + wc;
            float4 s0 = *(const float4*)(srow);
            float4 s1 = *(const float4*)(srow + 4);
            float p0 = exp_small(s0.x * 0.0078125f);
            float p1 = exp_small(s0.y * 0.0078125f);
            float p2 = exp_small(s0.z * 0.0078125f);
            float p3 = exp_small(s0.w * 0.0078125f);
            float p4 = exp_small(s1.x * 0.0078125f);
            float p5 = exp_small(s1.y * 0.0078125f);
            float p6 = exp_small(s1.z * 0.0078125f);
            float p7 = exp_small(s1.w * 0.0078125f);
            p0 = (pm0.x != 0.0f) ? 0.0f : p0;
            p1 = (pm0.y != 0.0f) ? 0.0f : p1;
            p2 = (pm0.z != 0.0f) ? 0.0f : p2;
            p3 = (pm0.w != 0.0f) ? 0.0f : p3;
            p4 = (pm1.x != 0.0f) ? 0.0f : p4;
            p5 = (pm1.y != 0.0f) ? 0.0f : p5;
            p6 = (pm1.z != 0.0f) ? 0.0f : p6;
            p7 = (pm1.w != 0.0f) ? 0.0f : p7;
            if (awbase) {
                *(float4*)(awbase + (long long)kt * TK) = make_float4(p0, p1, p2, p3);
                *(float4*)(awbase + (long long)kt * TK + 4) = make_float4(p4, p5, p6, p7);
            }
            lsum += (p0 + p1) + (p2 + p3) + (p4 + p5) + (p6 + p7);
            __half2 h0 = __floats2half2_rn(p0, p1);
            __half2 h1 = __floats2half2_rn(p2, p3);
            __half2 h2 = __floats2half2_rn(p4, p5);
            __half2 h3 = __floats2half2_rn(p6, p7);
            uint4 u;
            u.x = *(unsigned*)&h0;
            u.y = *(unsigned*)&h1;
            u.z = *(unsigned*)&h2;
            u.w = *(unsigned*)&h3;
            *(uint4*)(Psh + wr * PLDH + wc) = u;
        }
        bar_sync(ti + 1, 128);   // only row-group ti's 4 warps must align for PV

        // PV: O += P * V (A reads Psh rows ti, written by group ti)
        #pragma unroll
        for (int k = 0; k < TK / 16; ++k) {
            wmma::fragment<wmma::matrix_a, 16, 16, 16, __half, wmma::row_major> af;
            wmma::load_matrix_sync(af, Psh + ti * 16 * PLDH + k * 16, PLDH);
            #pragma unroll
            for (int jj = 0; jj < 2; ++jj) {
                wmma::fragment<wmma::matrix_b, 16, 16, 16, __half, wmma::row_major> bf;
                wmma::load_matrix_sync(bf, Vc + k * 16 * LDH + (tj * 2 + jj) * 16, LDH);
                wmma::mma_sync(Oacc[jj], af, bf, Oacc[jj]);
            }
        }
    }

    // Row sums: combine the 2 lanes per row, publish per-tj partials, reduce
    lsum += __shfl_xor_sync(0xffffffffu, lsum, 1);
    if ((lane & 1) == 0) {
        lrowP[tj * 64 + wr] = lsum;
    }
    __syncthreads();
    if (tid < 64) {
        lrowI[tid] = 1.0f / (lrowP[tid] + lrowP[64 + tid] +
                             lrowP[128 + tid] + lrowP[192 + tid]);
    }

    // Stage O (fp32) into the KV region, then normalized write
    float* Of = (float*)(sm + KV_OFF);
    #pragma unroll
    for (int jj = 0; jj < 2; ++jj) {
        wmma::store_matrix_sync(Of + ti * 16 * OLDF + (tj * 2 + jj) * 16, Oacc[jj],
                                OLDF, wmma::mem_row_major);
    }
    __syncthreads();

    {
        const int er = tid >> 3;
        const int c0 = (tid & 7) * 16;
        const float inv = lrowI[er];
        float* orow = outg + (bh * Sc + q0 + er) * (long long)Dc;
        #pragma unroll
        for (int cc = 0; cc < 4; ++cc) {
            int c = c0 + cc * 4;
            float4 o4 = *(const float4*)(Of + er * OLDF + c);
            o4.x *= inv;
            o4.y *= inv;
            o4.z *= inv;
            o4.w *= inv;
            *(float4*)(orow + c) = o4;
        }
    }
}

// Kernel 2: normalize each attn row in place (measured at DRAM roofline)
__global__ __launch_bounds__(256, 8)
void attn_norm_kernel(float* __restrict__ attn) {
    const long long row = blockIdx.x;
    float4* rp = (float4*)(attn + row * (long long)Sc);
    const int t = threadIdx.x;

    float4 a = rp[t];
    float4 b = rp[t + 256];
    float s = a.x + a.y + a.z + a.w + b.x + b.y + b.z + b.w;
    #pragma unroll
    for (int o = 16; o > 0; o >>= 1) {
        s += __shfl_xor_sync(0xffffffffu, s, o);
    }

    __shared__ float red[8];
    if ((t & 31) == 0) {
        red[t >> 5] = s;
    }
    __syncthreads();
    float tot = red[0] + red[1] + red[2] + red[3] + red[4] + red[5] + red[6] + red[7];
    float inv = 1.0f / tot;

    a.x *= inv; a.y *= inv; a.z *= inv; a.w *= inv;
    b.x *= inv; b.y *= inv; b.z *= inv; b.w *= inv;
    rp[t] = a;
    rp[t + 256] = b;
}

extern "C" void kernel_launch(void* const* d_in, const int* in_sizes, int n_in,
                              void* d_out, int out_size) {
    const float* q = (const float*)d_in[0];
    const float* k = (const float*)d_in[1];
    const float* v = (const float*)d_in[2];
    const float* m = (const float*)d_in[3];
    float* out = (float*)d_out;

    const long long OUT_ELE = (long long)Bc * Hc * Sc * Dc;
    float* attn = ((long long)out_size > OUT_ELE) ? (out + OUT_ELE) : nullptr;

    cudaFuncSetAttribute(attn_main_kernel,
                         cudaFuncAttributeMaxDynamicSharedMemorySize, SMEM_BYTES);
    cudaFuncSetAttribute(attn_main_kernel,
                         cudaFuncAttributePreferredSharedMemoryCarveout, 100);

    cvt_kernel<<<NTOT / 4 / 256, 256>>>((const float4*)q, (const float4*)k,
                                        (const float4*)v);

    dim3 grid1(Hc, Sc / TQ, Bc);
    attn_main_kernel<<<grid1, THREADS, SMEM_BYTES>>>(m, out, attn);

    if (attn) {
        attn_norm_kernel<<<(long long)Bc * Hc * Sc, 256>>>(attn);
    }
}

// round 17
// speedup vs baseline: 1.1406x; 1.1406x over previous
#include <cuda_runtime.h>
#include <cuda_fp16.h>
#include <mma.h>

using namespace nvcuda;

// Problem constants
#define Bc 4
#define Hc 16
#define Sc 2048
#define Dc 128
#define NTOT (Bc * Hc * Sc * Dc)

// Tiling (round-15 winning shape)
#define TQ 64
#define TK 64
#define THREADS 512
#define NKT (Sc / TK)
#define LDH  136
#define PLDF 68
#define PLDH 72
#define OLDF 132

// smem layout (bytes)
#define QH_OFF   0
#define KV_OFF   (TQ * LDH * 2)                 // 17408; 2 stages of (K tile, V tile)
#define KVSTAGE  (2 * TK * LDH * 2)             // 34816 per stage
#define PSF_OFF  (KV_OFF + 2 * KVSTAGE)         // 87040
#define PSH_OFF  (PSF_OFF + TQ * PLDF * 4)      // 104448
#define SMEM_BYTES (PSH_OFF + TQ * PLDH * 2)    // 113664 -> 2 CTAs/SM

// fp16 copies of Q/K/V (pre-pass output). Static device scratch: allowed.
__device__ __half g_qh[NTOT];
__device__ __half g_kh[NTOT];
__device__ __half g_vh[NTOT];

__device__ __forceinline__ void cp_async16(void* s, const void* g) {
    unsigned sa = (unsigned)__cvta_generic_to_shared(s);
    asm volatile("cp.async.cg.shared.global [%0],[%1],16;\n" ::"r"(sa), "l"(g));
}
__device__ __forceinline__ void cp_commit() { asm volatile("cp.async.commit_group;\n"); }
__device__ __forceinline__ void cp_wait0() { asm volatile("cp.async.wait_group 0;\n"); }
__device__ __forceinline__ void cp_wait1() { asm volatile("cp.async.wait_group 1;\n"); }

// exp for small x via degree-6 Taylor; __expf fallback for the rare tail
__device__ __forceinline__ float exp_small(float x) {
    float pe = 1.388888889e-3f;
    pe = fmaf(pe, x, 8.333333333e-3f);
    pe = fmaf(pe, x, 4.166666667e-2f);
    pe = fmaf(pe, x, 1.666666667e-1f);
    pe = fmaf(pe, x, 0.5f);
    pe = fmaf(pe, x, 1.0f);
    pe = fmaf(pe, x, 1.0f);
    if (fabsf(x) > 0.5f) {
        pe = __expf(x);
    }
    return pe;
}

// Pre-pass: fp32 to fp16 RN conversion of Q, K, V (measured 84% DRAM, 39us)
__global__ __launch_bounds__(256)
void cvt_kernel(const float4* __restrict__ q,
                const float4* __restrict__ k,
                const float4* __restrict__ v) {
    int i = blockIdx.x * blockDim.x + threadIdx.x;
    float4 a;
    __half2 h0, h1;
    uint2 u;

    a = q[i];
    h0 = __floats2half2_rn(a.x, a.y);
    h1 = __floats2half2_rn(a.z, a.w);
    u.x = *(unsigned*)&h0;
    u.y = *(unsigned*)&h1;
    ((uint2*)g_qh)[i] = u;

    a = k[i];
    h0 = __floats2half2_rn(a.x, a.y);
    h1 = __floats2half2_rn(a.z, a.w);
    u.x = *(unsigned*)&h0;
    u.y = *(unsigned*)&h1;
    ((uint2*)g_kh)[i] = u;

    a = v[i];
    h0 = __floats2half2_rn(a.x, a.y);
    h1 = __floats2half2_rn(a.z, a.w);
    u.x = *(unsigned*)&h0;
    u.y = *(unsigned*)&h1;
    ((uint2*)g_vh)[i] = u;
}

__global__ __launch_bounds__(THREADS, 2)
void attn_main_kernel(const float* __restrict__ mg,
                      float* __restrict__ outg,
                      float* __restrict__ attng) {
    extern __shared__ char sm[];
    __half* Qh  = (__half*)(sm + QH_OFF);
    __half* kvs = (__half*)(sm + KV_OFF);
    float*  Psf = (float*)(sm + PSF_OFF);
    __half* Psh = (__half*)(sm + PSH_OFF);

    const int hh = blockIdx.x;   // head fastest: mask slice L2-reused across heads
    const int qt = blockIdx.y;
    const int b  = blockIdx.z;
    const int tid  = threadIdx.x;
    const int warp = tid >> 5;
    const int q0   = qt * TQ;

    const long long bh = (long long)b * Hc + hh;
    const __half* qptr  = g_qh + (bh * Sc + q0) * (long long)Dc;
    const __half* kbase = g_kh + bh * Sc * (long long)Dc;
    const __half* vbase = g_vh + bh * Sc * (long long)Dc;

    // Prologue group 0: Q tile + K0/V0 into stage 0
    {
        int r = tid >> 4;
        int c8 = (tid & 15) * 8;
        cp_async16(Qh + r * LDH + c8, qptr + (long long)r * Dc + c8);
        cp_async16(kvs + r * LDH + c8, kbase + (long long)r * Dc + c8);
        cp_async16(kvs + TK * LDH + r * LDH + c8, vbase + (long long)r * Dc + c8);
        r += 32;
        cp_async16(Qh + r * LDH + c8, qptr + (long long)r * Dc + c8);
        cp_async16(kvs + r * LDH + c8, kbase + (long long)r * Dc + c8);
        cp_async16(kvs + TK * LDH + r * LDH + c8, vbase + (long long)r * Dc + c8);
    }
    cp_commit();

    const int ti = warp >> 2;
    const int tj = warp & 3;

    wmma::fragment<wmma::accumulator, 16, 16, 16, float> Oacc[2];
    wmma::fill_fragment(Oacc[0], 0.0f);
    wmma::fill_fragment(Oacc[1], 0.0f);
    float lsum = 0.0f;   // per-thread rowsum partial, reduced at the end

    // Exp-phase addressing (round-15 coalesced mapping: warp = 4 rows x 64 cols)
    const int er  = tid >> 3;
    const int ec0 = (tid & 7) * 8;
    const float* mrow = mg + ((long long)b * Sc + q0 + er) * (long long)Sc + ec0;
    float* arow = attng ? (attng + (bh * Sc + q0 + er) * (long long)Sc + ec0) : nullptr;

    for (int kt = 0; kt < NKT; ++kt) {
        // Mask register prefetch (addresses depend only on kt; hides L2 latency
        // under the cp.async issue + QK phase). Same coalesced mapping as R15.
        const float* mk = mrow + (long long)kt * TK;
        float4 pm0 = *(const float4*)(mk);
        float4 pm1 = *(const float4*)(mk + 4);

        __syncthreads();   // all warps done reading the stage we are about to refill

        if (kt + 1 < NKT) {
            const __half* kp = kbase + (long long)(kt + 1) * TK * Dc;
            const __half* vp = vbase + (long long)(kt + 1) * TK * Dc;
            __half* kd = kvs + ((kt + 1) & 1) * (KVSTAGE / 2);
            int r = tid >> 4;
            int c8 = (tid & 15) * 8;
            cp_async16(kd + r * LDH + c8, kp + (long long)r * Dc + c8);
            cp_async16(kd + TK * LDH + r * LDH + c8, vp + (long long)r * Dc + c8);
            r += 32;
            cp_async16(kd + r * LDH + c8, kp + (long long)r * Dc + c8);
            cp_async16(kd + TK * LDH + r * LDH + c8, vp + (long long)r * Dc + c8);
            cp_commit();
            cp_wait1();    // stage kt arrived; stage kt+1 still in flight
        } else {
            cp_wait0();
        }
        __syncthreads();   // stage kt (and Q on first iter) visible to all warps

        const __half* Kc = kvs + (kt & 1) * (KVSTAGE / 2);
        const __half* Vc = Kc + TK * LDH;

        // Scores: S = Q * K^T
        {
            wmma::fragment<wmma::accumulator, 16, 16, 16, float> Sacc;
            wmma::fill_fragment(Sacc, 0.0f);
            #pragma unroll
            for (int k = 0; k < Dc / 16; ++k) {
                wmma::fragment<wmma::matrix_a, 16, 16, 16, __half, wmma::row_major> af;
                wmma::fragment<wmma::matrix_b, 16, 16, 16, __half, wmma::col_major> bf;
                wmma::load_matrix_sync(af, Qh + ti * 16 * LDH + k * 16, LDH);
                wmma::load_matrix_sync(bf, Kc + tj * 16 * LDH + k * 16, LDH);
                wmma::mma_sync(Sacc, af, bf, Sacc);
            }
            wmma::store_matrix_sync(Psf + ti * 16 * PLDF + tj * 16, Sacc, PLDF,
                                    wmma::mem_row_major);
        }
        __syncthreads();   // Psf visible

        // Elementwise: p = mask ? 0 : exp(s/128); streaming attn store; P->fp16
        {
            const float* srow = Psf + er * PLDF + ec0;
            float* ak = arow ? (arow + (long long)kt * TK) : nullptr;
            float4 s0 = *(const float4*)(srow);
            float4 s1 = *(const float4*)(srow + 4);

            float p0 = exp_small(s0.x * 0.0078125f);
            float p1 = exp_small(s0.y * 0.0078125f);
            float p2 = exp_small(s0.z * 0.0078125f);
            float p3 = exp_small(s0.w * 0.0078125f);
            p0 = (pm0.x != 0.0f) ? 0.0f : p0;
            p1 = (pm0.y != 0.0f) ? 0.0f : p1;
            p2 = (pm0.z != 0.0f) ? 0.0f : p2;
            p3 = (pm0.w != 0.0f) ? 0.0f : p3;

            float p4 = exp_small(s1.x * 0.0078125f);
            float p5 = exp_small(s1.y * 0.0078125f);
            float p6 = exp_small(s1.z * 0.0078125f);
            float p7 = exp_small(s1.w * 0.0078125f);
            p4 = (pm1.x != 0.0f) ? 0.0f : p4;
            p5 = (pm1.y != 0.0f) ? 0.0f : p5;
            p6 = (pm1.z != 0.0f) ? 0.0f : p6;
            p7 = (pm1.w != 0.0f) ? 0.0f : p7;

            if (ak) {
                __stcs((float4*)(ak), make_float4(p0, p1, p2, p3));
                __stcs((float4*)(ak + 4), make_float4(p4, p5, p6, p7));
            }
            lsum += (p0 + p1) + (p2 + p3) + (p4 + p5) + (p6 + p7);

            __half2 h0 = __floats2half2_rn(p0, p1);
            __half2 h1 = __floats2half2_rn(p2, p3);
            __half2 h2 = __floats2half2_rn(p4, p5);
            __half2 h3 = __floats2half2_rn(p6, p7);
            uint4 u;
            u.x = *(unsigned*)&h0;
            u.y = *(unsigned*)&h1;
            u.z = *(unsigned*)&h2;
            u.w = *(unsigned*)&h3;
            *(uint4*)(Psh + er * PLDH + ec0) = u;
        }
        __syncthreads();   // Psh visible

        // PV: O += P * V
        #pragma unroll
        for (int k = 0; k < TK / 16; ++k) {
            wmma::fragment<wmma::matrix_a, 16, 16, 16, __half, wmma::row_major> af;
            wmma::load_matrix_sync(af, Psh + ti * 16 * PLDH + k * 16, PLDH);
            #pragma unroll
            for (int jj = 0; jj < 2; ++jj) {
                wmma::fragment<wmma::matrix_b, 16, 16, 16, __half, wmma::row_major> bf;
                wmma::load_matrix_sync(bf, Vc + k * 16 * LDH + (tj * 2 + jj) * 16, LDH);
                wmma::mma_sync(Oacc[jj], af, bf, Oacc[jj]);
            }
        }
    }

    // Row sums: the 8 lanes sharing row er reduce among themselves
    lsum += __shfl_xor_sync(0xffffffffu, lsum, 1);
    lsum += __shfl_xor_sync(0xffffffffu, lsum, 2);
    lsum += __shfl_xor_sync(0xffffffffu, lsum, 4);
    const float inv = 1.0f / lsum;

    __syncthreads();
    // Stage O (fp32) into the KV region, then normalized write
    float* Of = (float*)(sm + KV_OFF);
    #pragma unroll
    for (int jj = 0; jj < 2; ++jj) {
        wmma::store_matrix_sync(Of + ti * 16 * OLDF + (tj * 2 + jj) * 16, Oacc[jj],
                                OLDF, wmma::mem_row_major);
    }
    __syncthreads();

    {
        const int c0 = (tid & 7) * 16;
        float* orow = outg + (bh * Sc + q0 + er) * (long long)Dc;
        #pragma unroll
        for (int cc = 0; cc < 4; ++cc) {
            int c = c0 + cc * 4;
            float4 o4 = *(const float4*)(Of + er * OLDF + c);
            o4.x *= inv;
            o4.y *= inv;
            o4.z *= inv;
            o4.w *= inv;
            *(float4*)(orow + c) = o4;
        }
    }
}

// Kernel 2: normalize each attn row in place (measured at DRAM roofline)
__global__ __launch_bounds__(256, 8)
void attn_norm_kernel(float* __restrict__ attn) {
    const long long row = blockIdx.x;
    float4* rp = (float4*)(attn + row * (long long)Sc);
    const int t = threadIdx.x;

    float4 a = rp[t];
    float4 b = rp[t + 256];
    float s = a.x + a.y + a.z + a.w + b.x + b.y + b.z + b.w;
    #pragma unroll
    for (int o = 16; o > 0; o >>= 1) {
        s += __shfl_xor_sync(0xffffffffu, s, o);
    }

    __shared__ float red[8];
    if ((t & 31) == 0) {
        red[t >> 5] = s;
    }
    __syncthreads();
    float tot = red[0] + red[1] + red[2] + red[3] + red[4] + red[5] + red[6] + red[7];
    float inv = 1.0f / tot;

    a.x *= inv; a.y *= inv; a.z *= inv; a.w *= inv;
    b.x *= inv; b.y *= inv; b.z *= inv; b.w *= inv;
    rp[t] = a;
    rp[t + 256] = b;
}

extern "C" void kernel_launch(void* const* d_in, const int* in_sizes, int n_in,
                              void* d_out, int out_size) {
    const float* q = (const float*)d_in[0];
    const float* k = (const float*)d_in[1];
    const float* v = (const float*)d_in[2];
    const float* m = (const float*)d_in[3];
    float* out = (float*)d_out;

    const long long OUT_ELE = (long long)Bc * Hc * Sc * Dc;
    float* attn = ((long long)out_size > OUT_ELE) ? (out + OUT_ELE) : nullptr;

    cudaFuncSetAttribute(attn_main_kernel,
                         cudaFuncAttributeMaxDynamicSharedMemorySize, SMEM_BYTES);
    cudaFuncSetAttribute(attn_main_kernel,
                         cudaFuncAttributePreferredSharedMemoryCarveout, 100);

    cvt_kernel<<<NTOT / 4 / 256, 256>>>((const float4*)q, (const float4*)k,
                                        (const float4*)v);

    dim3 grid1(Hc, Sc / TQ, Bc);
    attn_main_kernel<<<grid1, THREADS, SMEM_BYTES>>>(m, out, attn);

    if (attn) {
        attn_norm_kernel<<<(long long)Bc * Hc * Sc, 256>>>(attn);
    }
}